// round 3
// baseline (speedup 1.0000x reference)
#include <cuda_runtime.h>

#define NPG    1430
#define GENE0  1421
#define NHEADS 9

static const int MAXN = 732160;           // 1430 * 512 nodes
static const int MAXA = 512 * NHEADS * 16; // agg2 accumulator
static const int GCAP = 262144;            // gene-edge list capacity (expected ~37K)

// Scratch (allocation-free: __device__ globals)
__device__ int   g_degi[MAXN];
__device__ float g_dinv[MAXN];
__device__ float g_u[MAXN];      // dinv[n] * x[n]
__device__ float g_raw[MAXN];    // sum over in-edges of u[src]
__device__ float g_t[MAXN];      // layer-1 aggregated scalar
__device__ float g_agg2[MAXA];   // layer-2 raw aggregation at gene nodes
__device__ int   g_glist[GCAP];  // edge ids whose dst is a gene node
__device__ int   g_gcount;

// ---------------------------------------------------------------------------
// Zero all accumulators (must run every replay; d_out/scratch are stateful)
// ---------------------------------------------------------------------------
__global__ void k_zero(int n4, int a4) {
    int i = blockIdx.x * blockDim.x + threadIdx.x;
    if (i < n4) {
        ((int4*)g_degi)[i]  = make_int4(0, 0, 0, 0);
        ((float4*)g_raw)[i] = make_float4(0.f, 0.f, 0.f, 0.f);
    }
    if (i < a4) ((float4*)g_agg2)[i] = make_float4(0.f, 0.f, 0.f, 0.f);
    if (i == 0) g_gcount = 0;
}

// ---------------------------------------------------------------------------
// Pass 1: in-degree count + compact list of edges landing on gene nodes
// ---------------------------------------------------------------------------
__global__ void k_deg(const int* __restrict__ dst, int e4, int E) {
    int i = blockIdx.x * blockDim.x + threadIdx.x;
    if (i >= e4) return;
    int4 d = __ldcs((const int4*)dst + i);
    int dd[4] = {d.x, d.y, d.z, d.w};
#pragma unroll
    for (int j = 0; j < 4; j++) {
        unsigned v = (unsigned)dd[j];
        atomicAdd(&g_degi[v], 1);
        unsigned q = v / (unsigned)NPG;
        if (v - q * (unsigned)NPG >= (unsigned)GENE0) {
            int p = atomicAdd(&g_gcount, 1);
            if (p < GCAP) g_glist[p] = i * 4 + j;
        }
    }
    // scalar tail (E not divisible by 4) — handled by thread 0
    if (i == 0) {
        for (int e = e4 * 4; e < E; e++) {
            unsigned v = (unsigned)__ldg(dst + e);
            atomicAdd(&g_degi[v], 1);
            unsigned q = v / (unsigned)NPG;
            if (v - q * (unsigned)NPG >= (unsigned)GENE0) {
                int p = atomicAdd(&g_gcount, 1);
                if (p < GCAP) g_glist[p] = e;
            }
        }
    }
}

// ---------------------------------------------------------------------------
// Per-node: dinv = rsqrt(deg+1), u = dinv * x
// ---------------------------------------------------------------------------
__global__ void k_node1(const float* __restrict__ x, int n4, int N) {
    int i = blockIdx.x * blockDim.x + threadIdx.x;
    if (i >= n4) return;
    int4   dg = ((const int4*)g_degi)[i];
    float4 xv = __ldg((const float4*)x + i);
    float4 dv, uv;
    dv.x = rsqrtf((float)dg.x + 1.0f); uv.x = dv.x * xv.x;
    dv.y = rsqrtf((float)dg.y + 1.0f); uv.y = dv.y * xv.y;
    dv.z = rsqrtf((float)dg.z + 1.0f); uv.z = dv.z * xv.z;
    dv.w = rsqrtf((float)dg.w + 1.0f); uv.w = dv.w * xv.w;
    ((float4*)g_dinv)[i] = dv;
    ((float4*)g_u)[i]    = uv;
    if (i == 0) {
        for (int n = n4 * 4; n < N; n++) {
            float d = rsqrtf((float)g_degi[n] + 1.0f);
            g_dinv[n] = d;
            g_u[n]    = d * __ldg(x + n);
        }
    }
}

// ---------------------------------------------------------------------------
// Pass 2: scalar layer-1 scatter: raw[dst] += u[src]
// ---------------------------------------------------------------------------
__global__ void k_scatter(const int* __restrict__ src, const int* __restrict__ dst,
                          int e4, int E) {
    int i = blockIdx.x * blockDim.x + threadIdx.x;
    if (i >= e4) return;
    int4 s = __ldcs((const int4*)src + i);
    int4 d = __ldcs((const int4*)dst + i);
    atomicAdd(&g_raw[d.x], __ldg(&g_u[s.x]));
    atomicAdd(&g_raw[d.y], __ldg(&g_u[s.y]));
    atomicAdd(&g_raw[d.z], __ldg(&g_u[s.z]));
    atomicAdd(&g_raw[d.w], __ldg(&g_u[s.w]));
    if (i == 0) {
        for (int e = e4 * 4; e < E; e++)
            atomicAdd(&g_raw[__ldg(dst + e)], __ldg(&g_u[__ldg(src + e)]));
    }
}

// ---------------------------------------------------------------------------
// Per-node: t = dinv * (raw + u)   (layer-1 aggregated scalar, pre-W1)
// ---------------------------------------------------------------------------
__global__ void k_t(int n4, int N) {
    int i = blockIdx.x * blockDim.x + threadIdx.x;
    if (i >= n4) return;
    float4 r  = ((const float4*)g_raw)[i];
    float4 u  = ((const float4*)g_u)[i];
    float4 dv = ((const float4*)g_dinv)[i];
    float4 t;
    t.x = dv.x * (r.x + u.x);
    t.y = dv.y * (r.y + u.y);
    t.z = dv.z * (r.z + u.z);
    t.w = dv.w * (r.w + u.w);
    ((float4*)g_t)[i] = t;
    if (i == 0) {
        for (int n = n4 * 4; n < N; n++)
            g_t[n] = g_dinv[n] * (g_raw[n] + g_u[n]);
    }
}

// m[c] = sum_k relu(t*W1[k]+b1[k]) * W2[k][c]
__device__ __forceinline__ void compute_m(float t, const float* W1, const float* b1,
                                          const float* W2, float* m) {
#pragma unroll
    for (int c = 0; c < 16; c++) m[c] = 0.f;
#pragma unroll
    for (int k = 0; k < 16; k++) {
        float h = fmaxf(fmaf(t, W1[k], b1[k]), 0.f);
#pragma unroll
        for (int c = 0; c < 16; c++) m[c] = fmaf(h, W2[k * 16 + c], m[c]);
    }
}

// ---------------------------------------------------------------------------
// Pass 3: layer-2 scatter restricted to gene-destination edges
//   agg2[gene][c] += dinv[src] * m[src][c]
// ---------------------------------------------------------------------------
__global__ void k_l2(const int* __restrict__ src, const int* __restrict__ dst,
                     const float* __restrict__ W1, const float* __restrict__ b1,
                     const float* __restrict__ W2) {
    __shared__ float sW1[16], sb1[16], sW2[256];
    int tid = threadIdx.x;
    if (tid < 16) { sW1[tid] = W1[tid]; sb1[tid] = b1[tid]; }
    for (int j = tid; j < 256; j += blockDim.x) sW2[j] = W2[j];
    __syncthreads();

    int i = blockIdx.x * blockDim.x + tid;
    int cnt = g_gcount;
    if (cnt > GCAP) cnt = GCAP;
    if (i >= cnt) return;

    int e = g_glist[i];
    int s = __ldg(src + e);
    unsigned d = (unsigned)__ldg(dst + e);
    float ts = g_t[s];
    float ws = g_dinv[s];

    float m[16];
    compute_m(ts, sW1, sb1, sW2, m);

    unsigned gq = d / (unsigned)NPG;
    int head = (int)(d - gq * (unsigned)NPG) - GENE0;
    int gi = ((int)gq * NHEADS + head) * 16;
#pragma unroll
    for (int c = 0; c < 16; c++) atomicAdd(&g_agg2[gi + c], ws * m[c]);
}

// ---------------------------------------------------------------------------
// Final: per gene node, close layer 2 (self loop + scale + b2 + relu),
// then the per-head MLP.  tid -> head = tid / G  (warp-uniform head).
// ---------------------------------------------------------------------------
__global__ void k_final(const float* __restrict__ W1, const float* __restrict__ b1,
                        const float* __restrict__ W2, const float* __restrict__ b2,
                        const float* __restrict__ fw1, const float* __restrict__ fb1,
                        const float* __restrict__ fw2, const float* __restrict__ fb2,
                        float* __restrict__ out, int G) {
    int tid = blockIdx.x * blockDim.x + threadIdx.x;
    if (tid >= G * NHEADS) return;
    int head = tid / G;
    int g    = tid - head * G;
    int node = g * NPG + GENE0 + head;

    float tn = g_t[node];
    float dv = g_dinv[node];

    float m[16];
    compute_m(tn, W1, b1, W2, m);

    int gi = (g * NHEADS + head) * 16;
    float h2[16];
#pragma unroll
    for (int c = 0; c < 16; c++) {
        float a = dv * (g_agg2[gi + c] + dv * m[c]) + __ldg(b2 + c);
        h2[c] = fmaxf(a, 0.f);
    }

    float pred = __ldg(fb2 + head);
#pragma unroll
    for (int j = 0; j < 8; j++) {
        float z = __ldg(fb1 + head * 8 + j);
#pragma unroll
        for (int c = 0; c < 16; c++)
            z = fmaf(h2[c], __ldg(fw1 + head * 128 + c * 8 + j), z);
        z = fmaxf(z, 0.f);
        pred = fmaf(z, __ldg(fw2 + head * 8 + j), pred);
    }
    out[head * G + g] = pred;
}

// ---------------------------------------------------------------------------
extern "C" void kernel_launch(void* const* d_in, const int* in_sizes, int n_in,
                              void* d_out, int out_size) {
    const float* x   = (const float*)d_in[0];
    const int*   ei  = (const int*)  d_in[1];
    const float* W1  = (const float*)d_in[3];
    const float* b1  = (const float*)d_in[4];
    const float* W2  = (const float*)d_in[5];
    const float* b2  = (const float*)d_in[6];
    const float* fw1 = (const float*)d_in[7];
    const float* fb1 = (const float*)d_in[8];
    const float* fw2 = (const float*)d_in[9];
    const float* fb2 = (const float*)d_in[10];
    float* out = (float*)d_out;

    int N = in_sizes[0];             // x is [N,1]
    int E = in_sizes[1] / 2;         // edge_index is [2,E]
    int G = in_sizes[2] / NHEADS;    // y is [G*9]

    const int* src = ei;
    const int* dst = ei + E;

    int n4 = N / 4;
    int e4 = E / 4;
    int a4 = (G * NHEADS * 16) / 4;

    const int B = 256;
    int zmax = n4 > a4 ? n4 : a4;

    k_zero<<<(zmax + B - 1) / B, B>>>(n4, a4);
    k_deg<<<(e4 + B - 1) / B, B>>>(dst, e4, E);
    k_node1<<<(n4 + B - 1) / B, B>>>(x, n4, N);
    k_scatter<<<(e4 + B - 1) / B, B>>>(src, dst, e4, E);
    k_t<<<(n4 + B - 1) / B, B>>>(n4, N);
    k_l2<<<GCAP / B, B>>>(src, dst, W1, b1, W2);
    k_final<<<(G * NHEADS + 31) / 32, 32>>>(W1, b1, W2, b2, fw1, fb1, fw2, fb2, out, G);
}

// round 5
// speedup vs baseline: 1.1476x; 1.1476x over previous
#include <cuda_runtime.h>

#define NPG    1430
#define GENE0  1421
#define NHEADS 9

static const int MAXN = 732160;            // 1430 * 512 nodes
static const int MAXA = 512 * NHEADS * 16; // agg2 accumulator
static const int GCAP = 262144;            // gene-edge list capacity (expected ~37K)

// Scratch (allocation-free: __device__ globals)
__device__ int   g_degi[MAXN];
__device__ float g_dinv[MAXN];
__device__ float g_u[MAXN];      // dinv[n] * x[n]
__device__ float g_raw[MAXN];    // sum over in-edges of u[src]
__device__ float g_t[MAXN];      // layer-1 aggregated scalar
__device__ float g_agg2[MAXA];   // layer-2 raw aggregation at gene nodes
__device__ int   g_glist[GCAP];  // edge ids whose dst is a gene node
__device__ int   g_gcount;

// ---------------------------------------------------------------------------
// Zero degree counters + gene-edge counter (raw/agg2 zeroed in k_node1,
// which runs after k_deg and before any consumer of those arrays).
// ---------------------------------------------------------------------------
__global__ void k_zero(int n4) {
    int i = blockIdx.x * blockDim.x + threadIdx.x;
    if (i < n4) ((int4*)g_degi)[i] = make_int4(0, 0, 0, 0);
    if (i == 0) g_gcount = 0;
}

// ---------------------------------------------------------------------------
// Pass 1: in-degree count + compact list of edges landing on gene nodes.
// Gene-edge compaction uses a block-aggregated reservation: one shared-memory
// counter per block, a single global atomicAdd per block (no per-hit ATOMG
// round trip to the hot g_gcount address).
// ---------------------------------------------------------------------------
__global__ void k_deg(const int* __restrict__ dst, int e4) {
    __shared__ int s_cnt, s_base;
    if (threadIdx.x == 0) s_cnt = 0;
    __syncthreads();

    int i = blockIdx.x * blockDim.x + threadIdx.x;
    int hits[4];
    int c = 0;
    if (i < e4) {
        int4 d = __ldcs((const int4*)dst + i);
        int dd[4] = {d.x, d.y, d.z, d.w};
#pragma unroll
        for (int j = 0; j < 4; j++) {
            unsigned v = (unsigned)dd[j];
            atomicAdd(&g_degi[v], 1);
            unsigned q = v / (unsigned)NPG;
            if (v - q * (unsigned)NPG >= (unsigned)GENE0) hits[c++] = i * 4 + j;
        }
    }

    int my_off = 0;
    if (c) my_off = atomicAdd(&s_cnt, c);      // ATOMS, rare (~2.5% of threads)
    __syncthreads();
    if (threadIdx.x == 0) s_base = s_cnt ? atomicAdd(&g_gcount, s_cnt) : 0;
    __syncthreads();

    int base = s_base + my_off;
    for (int k = 0; k < c; k++) {
        int p = base + k;
        if (p < GCAP) g_glist[p] = hits[k];
    }
}

// ---------------------------------------------------------------------------
// Per-node: dinv = rsqrt(deg+1), u = dinv * x.  Also zeroes raw (consumed by
// k_scatter next) and agg2 (consumed by k_l2 later).
// ---------------------------------------------------------------------------
__global__ void k_node1(const float* __restrict__ x, int n4, int a4) {
    int i = blockIdx.x * blockDim.x + threadIdx.x;
    if (i < a4) ((float4*)g_agg2)[i] = make_float4(0.f, 0.f, 0.f, 0.f);
    if (i >= n4) return;
    int4   dg = ((const int4*)g_degi)[i];
    float4 xv = __ldg((const float4*)x + i);
    float4 dv, uv;
    dv.x = rsqrtf((float)dg.x + 1.0f); uv.x = dv.x * xv.x;
    dv.y = rsqrtf((float)dg.y + 1.0f); uv.y = dv.y * xv.y;
    dv.z = rsqrtf((float)dg.z + 1.0f); uv.z = dv.z * xv.z;
    dv.w = rsqrtf((float)dg.w + 1.0f); uv.w = dv.w * xv.w;
    ((float4*)g_dinv)[i] = dv;
    ((float4*)g_u)[i]    = uv;
    ((float4*)g_raw)[i]  = make_float4(0.f, 0.f, 0.f, 0.f);
}

// ---------------------------------------------------------------------------
// Pass 2: scalar layer-1 scatter: raw[dst] += u[src]   (LTS-roofline bound)
// ---------------------------------------------------------------------------
__global__ void k_scatter(const int* __restrict__ src, const int* __restrict__ dst,
                          int e4) {
    int i = blockIdx.x * blockDim.x + threadIdx.x;
    if (i >= e4) return;
    int4 s = __ldcs((const int4*)src + i);
    int4 d = __ldcs((const int4*)dst + i);
    atomicAdd(&g_raw[d.x], __ldg(&g_u[s.x]));
    atomicAdd(&g_raw[d.y], __ldg(&g_u[s.y]));
    atomicAdd(&g_raw[d.z], __ldg(&g_u[s.z]));
    atomicAdd(&g_raw[d.w], __ldg(&g_u[s.w]));
}

// ---------------------------------------------------------------------------
// Per-node: t = dinv * (raw + u)   (layer-1 aggregated scalar, pre-W1)
// ---------------------------------------------------------------------------
__global__ void k_t(int n4) {
    int i = blockIdx.x * blockDim.x + threadIdx.x;
    if (i >= n4) return;
    float4 r  = ((const float4*)g_raw)[i];
    float4 u  = ((const float4*)g_u)[i];
    float4 dv = ((const float4*)g_dinv)[i];
    float4 t;
    t.x = dv.x * (r.x + u.x);
    t.y = dv.y * (r.y + u.y);
    t.z = dv.z * (r.z + u.z);
    t.w = dv.w * (r.w + u.w);
    ((float4*)g_t)[i] = t;
}

// m[c] = sum_k relu(t*W1[k]+b1[k]) * W2[k][c]
__device__ __forceinline__ void compute_m(float t, const float* W1, const float* b1,
                                          const float* W2, float* m) {
#pragma unroll
    for (int c = 0; c < 16; c++) m[c] = 0.f;
#pragma unroll
    for (int k = 0; k < 16; k++) {
        float h = fmaxf(fmaf(t, W1[k], b1[k]), 0.f);
#pragma unroll
        for (int c = 0; c < 16; c++) m[c] = fmaf(h, W2[k * 16 + c], m[c]);
    }
}

// ---------------------------------------------------------------------------
// Pass 3: layer-2 scatter restricted to gene-destination edges
//   agg2[gene][c] += dinv[src] * m[src][c]
// ---------------------------------------------------------------------------
__global__ void k_l2(const int* __restrict__ src, const int* __restrict__ dst,
                     const float* __restrict__ W1, const float* __restrict__ b1,
                     const float* __restrict__ W2) {
    __shared__ float sW1[16], sb1[16], sW2[256];
    int tid = threadIdx.x;
    if (tid < 16) { sW1[tid] = W1[tid]; sb1[tid] = b1[tid]; }
    for (int j = tid; j < 256; j += blockDim.x) sW2[j] = W2[j];
    __syncthreads();

    int i = blockIdx.x * blockDim.x + tid;
    int cnt = g_gcount;
    if (cnt > GCAP) cnt = GCAP;
    if (i >= cnt) return;

    int e = g_glist[i];
    int s = __ldg(src + e);
    unsigned d = (unsigned)__ldg(dst + e);
    float ts = g_t[s];
    float ws = g_dinv[s];

    float m[16];
    compute_m(ts, sW1, sb1, sW2, m);

    unsigned gq = d / (unsigned)NPG;
    int head = (int)(d - gq * (unsigned)NPG) - GENE0;
    int gi = ((int)gq * NHEADS + head) * 16;
#pragma unroll
    for (int c = 0; c < 16; c++) atomicAdd(&g_agg2[gi + c], ws * m[c]);
}

// ---------------------------------------------------------------------------
// Final: per gene node, close layer 2 (self loop + scale + b2 + relu),
// then the per-head MLP.  tid -> head = tid / G  (warp-uniform head).
// ---------------------------------------------------------------------------
__global__ void k_final(const float* __restrict__ W1, const float* __restrict__ b1,
                        const float* __restrict__ W2, const float* __restrict__ b2,
                        const float* __restrict__ fw1, const float* __restrict__ fb1,
                        const float* __restrict__ fw2, const float* __restrict__ fb2,
                        float* __restrict__ out, int G) {
    int tid = blockIdx.x * blockDim.x + threadIdx.x;
    if (tid >= G * NHEADS) return;
    int head = tid / G;
    int g    = tid - head * G;
    int node = g * NPG + GENE0 + head;

    float tn = g_t[node];
    float dv = g_dinv[node];

    float m[16];
    compute_m(tn, W1, b1, W2, m);

    int gi = (g * NHEADS + head) * 16;
    float h2[16];
#pragma unroll
    for (int c = 0; c < 16; c++) {
        float a = dv * (g_agg2[gi + c] + dv * m[c]) + __ldg(b2 + c);
        h2[c] = fmaxf(a, 0.f);
    }

    float pred = __ldg(fb2 + head);
#pragma unroll
    for (int j = 0; j < 8; j++) {
        float z = __ldg(fb1 + head * 8 + j);
#pragma unroll
        for (int c = 0; c < 16; c++)
            z = fmaf(h2[c], __ldg(fw1 + head * 128 + c * 8 + j), z);
        z = fmaxf(z, 0.f);
        pred = fmaf(z, __ldg(fw2 + head * 8 + j), pred);
    }
    out[head * G + g] = pred;
}

// ---------------------------------------------------------------------------
extern "C" void kernel_launch(void* const* d_in, const int* in_sizes, int n_in,
                              void* d_out, int out_size) {
    const float* x   = (const float*)d_in[0];
    const int*   ei  = (const int*)  d_in[1];
    const float* W1  = (const float*)d_in[3];
    const float* b1  = (const float*)d_in[4];
    const float* W2  = (const float*)d_in[5];
    const float* b2  = (const float*)d_in[6];
    const float* fw1 = (const float*)d_in[7];
    const float* fb1 = (const float*)d_in[8];
    const float* fw2 = (const float*)d_in[9];
    const float* fb2 = (const float*)d_in[10];
    float* out = (float*)d_out;

    int N = in_sizes[0];             // x is [N,1]   (732160, div by 4)
    int E = in_sizes[1] / 2;         // edge_index is [2,E]  (E div by 4)
    int G = in_sizes[2] / NHEADS;    // y is [G*9]

    const int* src = ei;
    const int* dst = ei + E;

    int n4 = N / 4;
    int e4 = E / 4;
    int a4 = (G * NHEADS * 16) / 4;

    const int B = 256;

    k_zero<<<(n4 + B - 1) / B, B>>>(n4);
    k_deg<<<(e4 + B - 1) / B, B>>>(dst, e4);
    k_node1<<<(n4 + B - 1) / B, B>>>(x, n4, a4);
    k_scatter<<<(e4 + B - 1) / B, B>>>(src, dst, e4);
    k_t<<<(n4 + B - 1) / B, B>>>(n4);
    k_l2<<<GCAP / B, B>>>(src, dst, W1, b1, W2);
    k_final<<<(G * NHEADS + 31) / 32, 32>>>(W1, b1, W2, b2, fw1, fb1, fw2, fb2, out, G);
}

// round 7
// speedup vs baseline: 1.6854x; 1.4686x over previous
#include <cuda_runtime.h>

#define NPG    1430
#define GENE0  1421
#define NHEADS 9

static const int MAXN = 732160;            // 1430 * 512 nodes
static const int MAXA = 512 * NHEADS * 16; // agg2 accumulator
static const int GCAP = 262144;            // gene-edge list capacity (~37K expected)
static const int BMW  = MAXN / 32;         // bitmap words (22880)

// Scratch (allocation-free: __device__ globals)
__device__ int      g_degi[MAXN];
__device__ float    g_dinv[MAXN];
__device__ float    g_u[MAXN];       // dinv[n] * x[n]
__device__ float    g_raw[MAXN];     // sum over in-edges of u[src] (only valid at S)
__device__ float    g_agg2[MAXA];    // layer-2 raw aggregation at gene nodes
__device__ int      g_glist[GCAP];   // edge ids whose dst is a gene node
__device__ int      g_gcount;
__device__ unsigned g_bm[BMW];       // membership bitmap for S = {gene-edge srcs} U {gene dsts}

// ---------------------------------------------------------------------------
// Zero degree counters, bitmap, gene-edge counter.
// (raw/agg2 zeroed in k_node1, which runs after k_deg and before consumers.)
// ---------------------------------------------------------------------------
__global__ void k_zero(int n4) {
    int i = blockIdx.x * blockDim.x + threadIdx.x;
    if (i < n4) ((int4*)g_degi)[i] = make_int4(0, 0, 0, 0);
    if (i < BMW) g_bm[i] = 0u;
    if (i == 0) g_gcount = 0;
}

// ---------------------------------------------------------------------------
// Pass 1: in-degree count + gene-edge compaction + S-membership bitmap.
// Gene-dst detection is pure arithmetic (v % 1430 >= 1421). For each gene
// edge (rare, ~0.63%): record edge id, set bitmap bits for its src and dst.
// Gene-edge id reservation is block-aggregated (one global atomic per block).
// ---------------------------------------------------------------------------
__global__ void k_deg(const int* __restrict__ src, const int* __restrict__ dst,
                      int e4) {
    __shared__ int s_cnt, s_base;
    if (threadIdx.x == 0) s_cnt = 0;
    __syncthreads();

    int i = blockIdx.x * blockDim.x + threadIdx.x;
    int hits[4];
    int c = 0;
    if (i < e4) {
        int4 d = __ldcs((const int4*)dst + i);
        int dd[4] = {d.x, d.y, d.z, d.w};
#pragma unroll
        for (int j = 0; j < 4; j++) {
            unsigned v = (unsigned)dd[j];
            atomicAdd(&g_degi[v], 1);
            unsigned q = v / (unsigned)NPG;
            if (v - q * (unsigned)NPG >= (unsigned)GENE0) {
                int e = i * 4 + j;
                hits[c++] = e;
                unsigned s = (unsigned)__ldg(src + e);
                atomicOr(&g_bm[s >> 5], 1u << (s & 31u));   // src needs t
                atomicOr(&g_bm[v >> 5], 1u << (v & 31u));   // gene dst needs raw
            }
        }
    }

    int my_off = 0;
    if (c) my_off = atomicAdd(&s_cnt, c);
    __syncthreads();
    if (threadIdx.x == 0) s_base = s_cnt ? atomicAdd(&g_gcount, s_cnt) : 0;
    __syncthreads();

    int base = s_base + my_off;
    for (int k = 0; k < c; k++) {
        int p = base + k;
        if (p < GCAP) g_glist[p] = hits[k];
    }
}

// ---------------------------------------------------------------------------
// Per-node: dinv = rsqrt(deg+1), u = dinv * x.  Also zeroes raw and agg2.
// ---------------------------------------------------------------------------
__global__ void k_node1(const float* __restrict__ x, int n4, int a4) {
    int i = blockIdx.x * blockDim.x + threadIdx.x;
    if (i < a4) ((float4*)g_agg2)[i] = make_float4(0.f, 0.f, 0.f, 0.f);
    if (i >= n4) return;
    int4   dg = ((const int4*)g_degi)[i];
    float4 xv = __ldg((const float4*)x + i);
    float4 dv, uv;
    dv.x = rsqrtf((float)dg.x + 1.0f); uv.x = dv.x * xv.x;
    dv.y = rsqrtf((float)dg.y + 1.0f); uv.y = dv.y * xv.y;
    dv.z = rsqrtf((float)dg.z + 1.0f); uv.z = dv.z * xv.z;
    dv.w = rsqrtf((float)dg.w + 1.0f); uv.w = dv.w * xv.w;
    ((float4*)g_dinv)[i] = dv;
    ((float4*)g_u)[i]    = uv;
    ((float4*)g_raw)[i]  = make_float4(0.f, 0.f, 0.f, 0.f);
}

// ---------------------------------------------------------------------------
// Pass 2 (sparsified): raw[dst] += u[src] ONLY when dst is in S.
// One random access per edge (bitmap word); gather+RED only for the ~5.6%
// of edges whose dst feeds a later consumer.
// ---------------------------------------------------------------------------
__global__ void k_scatter(const int* __restrict__ src, const int* __restrict__ dst,
                          int e4) {
    int i = blockIdx.x * blockDim.x + threadIdx.x;
    if (i >= e4) return;
    int4 s4 = __ldcs((const int4*)src + i);
    int4 d4 = __ldcs((const int4*)dst + i);
    int ss[4] = {s4.x, s4.y, s4.z, s4.w};
    int dd[4] = {d4.x, d4.y, d4.z, d4.w};
#pragma unroll
    for (int j = 0; j < 4; j++) {
        unsigned v = (unsigned)dd[j];
        unsigned w = __ldg(&g_bm[v >> 5]);
        if ((w >> (v & 31u)) & 1u)
            atomicAdd(&g_raw[v], __ldg(&g_u[(unsigned)ss[j]]));
    }
}

// m[c] = sum_k relu(t*W1[k]+b1[k]) * W2[k][c]
__device__ __forceinline__ void compute_m(float t, const float* W1, const float* b1,
                                          const float* W2, float* m) {
#pragma unroll
    for (int c = 0; c < 16; c++) m[c] = 0.f;
#pragma unroll
    for (int k = 0; k < 16; k++) {
        float h = fmaxf(fmaf(t, W1[k], b1[k]), 0.f);
#pragma unroll
        for (int c = 0; c < 16; c++) m[c] = fmaf(h, W2[k * 16 + c], m[c]);
    }
}

// ---------------------------------------------------------------------------
// Pass 3: layer-2 scatter restricted to gene-destination edges
//   agg2[gene][c] += dinv[src] * m[src][c],  t computed inline.
// ---------------------------------------------------------------------------
__global__ void k_l2(const int* __restrict__ src, const int* __restrict__ dst,
                     const float* __restrict__ W1, const float* __restrict__ b1,
                     const float* __restrict__ W2) {
    __shared__ float sW1[16], sb1[16], sW2[256];
    int tid = threadIdx.x;
    if (tid < 16) { sW1[tid] = W1[tid]; sb1[tid] = b1[tid]; }
    for (int j = tid; j < 256; j += blockDim.x) sW2[j] = W2[j];
    __syncthreads();

    int i = blockIdx.x * blockDim.x + tid;
    int cnt = g_gcount;
    if (cnt > GCAP) cnt = GCAP;
    if (i >= cnt) return;

    int e = g_glist[i];
    int s = __ldg(src + e);
    unsigned d = (unsigned)__ldg(dst + e);
    float ws = g_dinv[s];
    float ts = ws * (g_raw[s] + g_u[s]);   // t computed inline (k_t eliminated)

    float m[16];
    compute_m(ts, sW1, sb1, sW2, m);

    unsigned gq = d / (unsigned)NPG;
    int head = (int)(d - gq * (unsigned)NPG) - GENE0;
    int gi = ((int)gq * NHEADS + head) * 16;
#pragma unroll
    for (int c = 0; c < 16; c++) atomicAdd(&g_agg2[gi + c], ws * m[c]);
}

// ---------------------------------------------------------------------------
// Final: per gene node, close layer 2 (self loop + scale + b2 + relu),
// then the per-head MLP.
// ---------------------------------------------------------------------------
__global__ void k_final(const float* __restrict__ W1, const float* __restrict__ b1,
                        const float* __restrict__ W2, const float* __restrict__ b2,
                        const float* __restrict__ fw1, const float* __restrict__ fb1,
                        const float* __restrict__ fw2, const float* __restrict__ fb2,
                        float* __restrict__ out, int G) {
    int tid = blockIdx.x * blockDim.x + threadIdx.x;
    if (tid >= G * NHEADS) return;
    int head = tid / G;
    int g    = tid - head * G;
    int node = g * NPG + GENE0 + head;

    float dv = g_dinv[node];
    float tn = dv * (g_raw[node] + g_u[node]);   // t inline

    float m[16];
    compute_m(tn, W1, b1, W2, m);

    int gi = (g * NHEADS + head) * 16;
    float h2[16];
#pragma unroll
    for (int c = 0; c < 16; c++) {
        float a = dv * (g_agg2[gi + c] + dv * m[c]) + __ldg(b2 + c);
        h2[c] = fmaxf(a, 0.f);
    }

    float pred = __ldg(fb2 + head);
#pragma unroll
    for (int j = 0; j < 8; j++) {
        float z = __ldg(fb1 + head * 8 + j);
#pragma unroll
        for (int c = 0; c < 16; c++)
            z = fmaf(h2[c], __ldg(fw1 + head * 128 + c * 8 + j), z);
        z = fmaxf(z, 0.f);
        pred = fmaf(z, __ldg(fw2 + head * 8 + j), pred);
    }
    out[head * G + g] = pred;
}

// ---------------------------------------------------------------------------
extern "C" void kernel_launch(void* const* d_in, const int* in_sizes, int n_in,
                              void* d_out, int out_size) {
    const float* x   = (const float*)d_in[0];
    const int*   ei  = (const int*)  d_in[1];
    const float* W1  = (const float*)d_in[3];
    const float* b1  = (const float*)d_in[4];
    const float* W2  = (const float*)d_in[5];
    const float* b2  = (const float*)d_in[6];
    const float* fw1 = (const float*)d_in[7];
    const float* fb1 = (const float*)d_in[8];
    const float* fw2 = (const float*)d_in[9];
    const float* fb2 = (const float*)d_in[10];
    float* out = (float*)d_out;

    int N = in_sizes[0];             // x is [N,1]   (732160, div by 4)
    int E = in_sizes[1] / 2;         // edge_index is [2,E]  (E div by 4)
    int G = in_sizes[2] / NHEADS;    // y is [G*9]

    const int* src = ei;
    const int* dst = ei + E;

    int n4 = N / 4;
    int e4 = E / 4;
    int a4 = (G * NHEADS * 16) / 4;

    const int B = 256;

    k_zero<<<(n4 + B - 1) / B, B>>>(n4);
    k_deg<<<(e4 + B - 1) / B, B>>>(src, dst, e4);
    k_node1<<<(n4 + B - 1) / B, B>>>(x, n4, a4);
    k_scatter<<<(e4 + B - 1) / B, B>>>(src, dst, e4);
    k_l2<<<GCAP / B, B>>>(src, dst, W1, b1, W2);
    k_final<<<(G * NHEADS + 31) / 32, 32>>>(W1, b1, W2, b2, fw1, fb1, fw2, fb2, out, G);
}

// round 8
// speedup vs baseline: 1.6965x; 1.0066x over previous
#include <cuda_runtime.h>

#define NPG    1430
#define GENE0  1421
#define NHEADS 9

static const int MAXN = 732160;            // 1430 * 512 nodes
static const int MAXA = 512 * NHEADS * 16; // agg2 accumulator
static const int GCAP = 262144;            // gene-edge list capacity (~37K expected)
static const int BMW  = MAXN / 32;         // bitmap words (22880)

// Scratch (allocation-free: __device__ globals; zero-initialized at load).
// Self-cleaning invariant: every kernel_launch leaves degi/bm/gcount zeroed
// (by k_node1 / k_l2 / k_final respectively), so no upfront zero pass.
__device__ int      g_degi[MAXN];
__device__ float    g_dinv[MAXN];
__device__ float    g_u[MAXN];       // dinv[n] * x[n]
__device__ float    g_raw[MAXN];     // sum over in-edges of u[src] (valid at S only)
__device__ float    g_agg2[MAXA];    // layer-2 raw aggregation at gene nodes
__device__ int      g_glist[GCAP];   // edge ids whose dst is a gene node
__device__ int      g_gcount;
__device__ unsigned g_bm[BMW];       // bitmap: S = {gene-edge srcs} U {gene dsts}

// ---------------------------------------------------------------------------
// Pass 1: in-degree count + gene-edge compaction + S-membership bitmap.
// Gene-dst detection is pure arithmetic (v % 1430 >= 1421). For each gene
// edge (~0.63%): record edge id, set bitmap bits for its src and dst.
// Gene-edge id reservation is block-aggregated (one global atomic per block).
// ---------------------------------------------------------------------------
__global__ void k_deg(const int* __restrict__ src, const int* __restrict__ dst,
                      int e4) {
    __shared__ int s_cnt, s_base;
    if (threadIdx.x == 0) s_cnt = 0;
    __syncthreads();

    int i = blockIdx.x * blockDim.x + threadIdx.x;
    int hits[4];
    int c = 0;
    if (i < e4) {
        int4 d = __ldcs((const int4*)dst + i);
        int dd[4] = {d.x, d.y, d.z, d.w};
#pragma unroll
        for (int j = 0; j < 4; j++) {
            unsigned v = (unsigned)dd[j];
            atomicAdd(&g_degi[v], 1);
            unsigned q = v / (unsigned)NPG;
            if (v - q * (unsigned)NPG >= (unsigned)GENE0) {
                int e = i * 4 + j;
                hits[c++] = e;
                unsigned s = (unsigned)__ldg(src + e);
                atomicOr(&g_bm[s >> 5], 1u << (s & 31u));   // src needs t
                atomicOr(&g_bm[v >> 5], 1u << (v & 31u));   // gene dst needs raw
            }
        }
    }

    int my_off = 0;
    if (c) my_off = atomicAdd(&s_cnt, c);
    __syncthreads();
    if (threadIdx.x == 0) s_base = s_cnt ? atomicAdd(&g_gcount, s_cnt) : 0;
    __syncthreads();

    int base = s_base + my_off;
    for (int k = 0; k < c; k++) {
        int p = base + k;
        if (p < GCAP) g_glist[p] = hits[k];
    }
}

// ---------------------------------------------------------------------------
// Per-node: dinv = rsqrt(deg+1), u = dinv * x.  Zeroes raw and agg2 (for the
// accumulators used later this replay) and degi (restoring the invariant for
// the NEXT replay — k_node1 is degi's only consumer).
// ---------------------------------------------------------------------------
__global__ void k_node1(const float* __restrict__ x, int n4, int a4) {
    int i = blockIdx.x * blockDim.x + threadIdx.x;
    if (i < a4) ((float4*)g_agg2)[i] = make_float4(0.f, 0.f, 0.f, 0.f);
    if (i >= n4) return;
    int4   dg = ((const int4*)g_degi)[i];
    float4 xv = __ldg((const float4*)x + i);
    float4 dv, uv;
    dv.x = rsqrtf((float)dg.x + 1.0f); uv.x = dv.x * xv.x;
    dv.y = rsqrtf((float)dg.y + 1.0f); uv.y = dv.y * xv.y;
    dv.z = rsqrtf((float)dg.z + 1.0f); uv.z = dv.z * xv.z;
    dv.w = rsqrtf((float)dg.w + 1.0f); uv.w = dv.w * xv.w;
    ((float4*)g_dinv)[i] = dv;
    ((float4*)g_u)[i]    = uv;
    ((float4*)g_raw)[i]  = make_float4(0.f, 0.f, 0.f, 0.f);
    ((int4*)g_degi)[i]   = make_int4(0, 0, 0, 0);     // self-clean for next replay
}

// ---------------------------------------------------------------------------
// Pass 2 (sparsified): raw[dst] += u[src] ONLY when dst is in S (~5.6% of
// edges). One random access per edge (bitmap word, L1/L2-resident); src is
// loaded SCALAR and only on a hit — no full src stream.
// ---------------------------------------------------------------------------
__global__ void k_scatter(const int* __restrict__ src, const int* __restrict__ dst,
                          int e4) {
    int i = blockIdx.x * blockDim.x + threadIdx.x;
    if (i >= e4) return;
    int4 d4 = __ldcs((const int4*)dst + i);
    int dd[4] = {d4.x, d4.y, d4.z, d4.w};
#pragma unroll
    for (int j = 0; j < 4; j++) {
        unsigned v = (unsigned)dd[j];
        unsigned w = __ldg(&g_bm[v >> 5]);
        if ((w >> (v & 31u)) & 1u) {
            unsigned s = (unsigned)__ldg(src + i * 4 + j);
            atomicAdd(&g_raw[v], __ldg(&g_u[s]));
        }
    }
}

// m[c] = sum_k relu(t*W1[k]+b1[k]) * W2[k][c]
__device__ __forceinline__ void compute_m(float t, const float* W1, const float* b1,
                                          const float* W2, float* m) {
#pragma unroll
    for (int c = 0; c < 16; c++) m[c] = 0.f;
#pragma unroll
    for (int k = 0; k < 16; k++) {
        float h = fmaxf(fmaf(t, W1[k], b1[k]), 0.f);
#pragma unroll
        for (int c = 0; c < 16; c++) m[c] = fmaf(h, W2[k * 16 + c], m[c]);
    }
}

// ---------------------------------------------------------------------------
// Pass 3: layer-2 scatter restricted to gene-destination edges
//   agg2[gene][c] += dinv[src] * m[src][c],  t computed inline.
// Also zeroes the bitmap (its reader k_scatter has completed).
// ---------------------------------------------------------------------------
__global__ void k_l2(const int* __restrict__ src, const int* __restrict__ dst,
                     const float* __restrict__ W1, const float* __restrict__ b1,
                     const float* __restrict__ W2) {
    __shared__ float sW1[16], sb1[16], sW2[256];
    int tid = threadIdx.x;
    if (tid < 16) { sW1[tid] = W1[tid]; sb1[tid] = b1[tid]; }
    for (int j = tid; j < 256; j += blockDim.x) sW2[j] = W2[j];
    __syncthreads();

    int i = blockIdx.x * blockDim.x + tid;
    if (i < BMW) g_bm[i] = 0u;                 // self-clean for next replay

    int cnt = g_gcount;
    if (cnt > GCAP) cnt = GCAP;
    if (i >= cnt) return;

    int e = g_glist[i];
    int s = __ldg(src + e);
    unsigned d = (unsigned)__ldg(dst + e);
    float ws = g_dinv[s];
    float ts = ws * (g_raw[s] + g_u[s]);       // t computed inline

    float m[16];
    compute_m(ts, sW1, sb1, sW2, m);

    unsigned gq = d / (unsigned)NPG;
    int head = (int)(d - gq * (unsigned)NPG) - GENE0;
    int gi = ((int)gq * NHEADS + head) * 16;
#pragma unroll
    for (int c = 0; c < 16; c++) atomicAdd(&g_agg2[gi + c], ws * m[c]);
}

// ---------------------------------------------------------------------------
// Final: per gene node, close layer 2 (self loop + scale + b2 + relu),
// then the per-head MLP.  Also zeroes gcount (reader k_l2 has completed).
// ---------------------------------------------------------------------------
__global__ void k_final(const float* __restrict__ W1, const float* __restrict__ b1,
                        const float* __restrict__ W2, const float* __restrict__ b2,
                        const float* __restrict__ fw1, const float* __restrict__ fb1,
                        const float* __restrict__ fw2, const float* __restrict__ fb2,
                        float* __restrict__ out, int G) {
    int tid = blockIdx.x * blockDim.x + threadIdx.x;
    if (tid == 0) g_gcount = 0;                // self-clean for next replay
    if (tid >= G * NHEADS) return;
    int head = tid / G;
    int g    = tid - head * G;
    int node = g * NPG + GENE0 + head;

    float dv = g_dinv[node];
    float tn = dv * (g_raw[node] + g_u[node]); // t inline

    float m[16];
    compute_m(tn, W1, b1, W2, m);

    int gi = (g * NHEADS + head) * 16;
    float h2[16];
#pragma unroll
    for (int c = 0; c < 16; c++) {
        float a = dv * (g_agg2[gi + c] + dv * m[c]) + __ldg(b2 + c);
        h2[c] = fmaxf(a, 0.f);
    }

    float pred = __ldg(fb2 + head);
#pragma unroll
    for (int j = 0; j < 8; j++) {
        float z = __ldg(fb1 + head * 8 + j);
#pragma unroll
        for (int c = 0; c < 16; c++)
            z = fmaf(h2[c], __ldg(fw1 + head * 128 + c * 8 + j), z);
        z = fmaxf(z, 0.f);
        pred = fmaf(z, __ldg(fw2 + head * 8 + j), pred);
    }
    out[head * G + g] = pred;
}

// ---------------------------------------------------------------------------
extern "C" void kernel_launch(void* const* d_in, const int* in_sizes, int n_in,
                              void* d_out, int out_size) {
    const float* x   = (const float*)d_in[0];
    const int*   ei  = (const int*)  d_in[1];
    const float* W1  = (const float*)d_in[3];
    const float* b1  = (const float*)d_in[4];
    const float* W2  = (const float*)d_in[5];
    const float* b2  = (const float*)d_in[6];
    const float* fw1 = (const float*)d_in[7];
    const float* fb1 = (const float*)d_in[8];
    const float* fw2 = (const float*)d_in[9];
    const float* fb2 = (const float*)d_in[10];
    float* out = (float*)d_out;

    int N = in_sizes[0];             // x is [N,1]   (732160, div by 4)
    int E = in_sizes[1] / 2;         // edge_index is [2,E]  (E div by 4)
    int G = in_sizes[2] / NHEADS;    // y is [G*9]

    const int* src = ei;
    const int* dst = ei + E;

    int n4 = N / 4;
    int e4 = E / 4;
    int a4 = (G * NHEADS * 16) / 4;

    const int B = 256;

    k_deg<<<(e4 + B - 1) / B, B>>>(src, dst, e4);
    k_node1<<<(n4 + B - 1) / B, B>>>(x, n4, a4);
    k_scatter<<<(e4 + B - 1) / B, B>>>(src, dst, e4);
    k_l2<<<GCAP / B, B>>>(src, dst, W1, b1, W2);
    k_final<<<(G * NHEADS + 31) / 32, 32>>>(W1, b1, W2, b2, fw1, fb1, fw2, fb2, out, G);
}

// round 9
// speedup vs baseline: 1.7450x; 1.0286x over previous
#include <cuda_runtime.h>

#define NPG    1430
#define GENE0  1421
#define NHEADS 9

static const int MAXN = 732160;            // 1430 * 512 nodes
static const int MAXA = 512 * NHEADS * 16; // agg2 accumulator
static const int GCAP = 262144;            // gene-edge list capacity (~37K expected)
static const int BMW  = MAXN / 32;         // bitmap words (22880)

// Scratch (allocation-free: __device__ globals; zero-initialized at load).
// Self-cleaning invariant: every kernel_launch leaves degi/bm/gcount zeroed
// (by k_node1 / k_l2 / k_final respectively), so no upfront zero pass.
__device__ int      g_degi[MAXN];
__device__ float    g_dinv[MAXN];
__device__ float    g_u[MAXN];       // dinv[n] * x[n]
__device__ float    g_raw[MAXN];     // sum over in-edges of u[src] (valid at S only)
__device__ float    g_agg2[MAXA];    // layer-2 raw aggregation at gene nodes
__device__ int      g_glist[GCAP];   // edge ids whose dst is a gene node
__device__ int      g_gcount;
__device__ unsigned g_bm[BMW];       // bitmap: S = {gene-edge srcs} U {gene dsts}

// ---------------------------------------------------------------------------
// Pass 1: in-degree count + gene-edge compaction + S-membership bitmap.
// Gene-dst detection is pure arithmetic (v % 1430 >= 1421). For each gene
// edge (~0.63%): record edge id, set bitmap bits for its src and dst.
// Gene-edge id reservation is block-aggregated (one global atomic per block).
// ---------------------------------------------------------------------------
__global__ void k_deg(const int* __restrict__ src, const int* __restrict__ dst,
                      int e4) {
    __shared__ int s_cnt, s_base;
    if (threadIdx.x == 0) s_cnt = 0;
    __syncthreads();

    int i = blockIdx.x * blockDim.x + threadIdx.x;
    int hits[4];
    int c = 0;
    if (i < e4) {
        int4 d = __ldcs((const int4*)dst + i);
        int dd[4] = {d.x, d.y, d.z, d.w};
#pragma unroll
        for (int j = 0; j < 4; j++) {
            unsigned v = (unsigned)dd[j];
            atomicAdd(&g_degi[v], 1);
            unsigned q = v / (unsigned)NPG;
            if (v - q * (unsigned)NPG >= (unsigned)GENE0) {
                int e = i * 4 + j;
                hits[c++] = e;
                unsigned s = (unsigned)__ldg(src + e);
                atomicOr(&g_bm[s >> 5], 1u << (s & 31u));   // src needs t
                atomicOr(&g_bm[v >> 5], 1u << (v & 31u));   // gene dst needs raw
            }
        }
    }

    int my_off = 0;
    if (c) my_off = atomicAdd(&s_cnt, c);
    __syncthreads();
    if (threadIdx.x == 0) s_base = s_cnt ? atomicAdd(&g_gcount, s_cnt) : 0;
    __syncthreads();

    int base = s_base + my_off;
    for (int k = 0; k < c; k++) {
        int p = base + k;
        if (p < GCAP) g_glist[p] = hits[k];
    }
}

// ---------------------------------------------------------------------------
// Per-node: dinv = rsqrt(deg+1), u = dinv * x.  Zeroes raw and agg2 (for the
// accumulators used later this replay) and degi (restoring the invariant for
// the NEXT replay — k_node1 is degi's only consumer).
// ---------------------------------------------------------------------------
__global__ void k_node1(const float* __restrict__ x, int n4, int a4) {
    int i = blockIdx.x * blockDim.x + threadIdx.x;
    if (i < a4) ((float4*)g_agg2)[i] = make_float4(0.f, 0.f, 0.f, 0.f);
    if (i >= n4) return;
    int4   dg = ((const int4*)g_degi)[i];
    float4 xv = __ldg((const float4*)x + i);
    float4 dv, uv;
    dv.x = rsqrtf((float)dg.x + 1.0f); uv.x = dv.x * xv.x;
    dv.y = rsqrtf((float)dg.y + 1.0f); uv.y = dv.y * xv.y;
    dv.z = rsqrtf((float)dg.z + 1.0f); uv.z = dv.z * xv.z;
    dv.w = rsqrtf((float)dg.w + 1.0f); uv.w = dv.w * xv.w;
    ((float4*)g_dinv)[i] = dv;
    ((float4*)g_u)[i]    = uv;
    ((float4*)g_raw)[i]  = make_float4(0.f, 0.f, 0.f, 0.f);
    ((int4*)g_degi)[i]   = make_int4(0, 0, 0, 0);     // self-clean for next replay
}

// ---------------------------------------------------------------------------
// Pass 2 (sparsified): raw[dst] += u[src] ONLY when dst is in S (~5.6% of
// edges). One random access per edge (bitmap word, mostly L1-resident);
// src is loaded SCALAR and only on a hit — no full src stream.
// ---------------------------------------------------------------------------
__global__ void k_scatter(const int* __restrict__ src, const int* __restrict__ dst,
                          int e4) {
    int i = blockIdx.x * blockDim.x + threadIdx.x;
    if (i >= e4) return;
    int4 d4 = __ldcs((const int4*)dst + i);
    int dd[4] = {d4.x, d4.y, d4.z, d4.w};
#pragma unroll
    for (int j = 0; j < 4; j++) {
        unsigned v = (unsigned)dd[j];
        unsigned w = __ldg(&g_bm[v >> 5]);
        if ((w >> (v & 31u)) & 1u) {
            unsigned s = (unsigned)__ldg(src + i * 4 + j);
            atomicAdd(&g_raw[v], __ldg(&g_u[s]));
        }
    }
}

// ---------------------------------------------------------------------------
// Pass 3: layer-2 scatter restricted to gene-destination edges.
// 16 LANES PER EDGE: lane c computes only channel c and issues ONE atomic;
// the 16 lane-atomics coalesce into a single 64B-line wavefront per edge
// (was: 16 serialized ATOMG round-trips from one thread). Shared-address
// loads broadcast within the lane group. Grid-stride over edge groups.
// Also zeroes the bitmap (its reader k_scatter has completed).
// ---------------------------------------------------------------------------
__global__ void k_l2(const int* __restrict__ src, const int* __restrict__ dst,
                     const float* __restrict__ W1, const float* __restrict__ b1,
                     const float* __restrict__ W2) {
    __shared__ float sW1[16], sb1[16], sW2[256];
    int tid = threadIdx.x;
    if (tid < 16) { sW1[tid] = W1[tid]; sb1[tid] = b1[tid]; }
    for (int j = tid; j < 256; j += blockDim.x) sW2[j] = W2[j];
    __syncthreads();

    int flat = blockIdx.x * blockDim.x + tid;
    if (flat < BMW) g_bm[flat] = 0u;           // self-clean for next replay

    int cnt = g_gcount;
    if (cnt > GCAP) cnt = GCAP;

    int lane    = tid & 15;
    int group   = flat >> 4;
    int gstride = (gridDim.x * blockDim.x) >> 4;

    for (int g = group; g < cnt; g += gstride) {
        int e = __ldg(&g_glist[g]);
        int s = __ldg(src + e);
        unsigned d = (unsigned)__ldg(dst + e);
        float ws = __ldg(&g_dinv[s]);
        float ts = ws * (__ldg(&g_raw[s]) + __ldg(&g_u[s]));  // t inline

        float m = 0.f;
#pragma unroll
        for (int k = 0; k < 16; k++) {
            float h = fmaxf(fmaf(ts, sW1[k], sb1[k]), 0.f);
            m = fmaf(h, sW2[k * 16 + lane], m);
        }

        unsigned gq = d / (unsigned)NPG;
        int head = (int)(d - gq * (unsigned)NPG) - GENE0;
        int gi = ((int)gq * NHEADS + head) * 16;
        atomicAdd(&g_agg2[gi + lane], ws * m);
    }
}

// ---------------------------------------------------------------------------
// Final: per gene node, close layer 2 (self loop + scale + b2 + relu),
// then the per-head MLP.  Also zeroes gcount (reader k_l2 has completed).
// ---------------------------------------------------------------------------
__global__ void k_final(const float* __restrict__ W1, const float* __restrict__ b1,
                        const float* __restrict__ W2, const float* __restrict__ b2,
                        const float* __restrict__ fw1, const float* __restrict__ fb1,
                        const float* __restrict__ fw2, const float* __restrict__ fb2,
                        float* __restrict__ out, int G) {
    int tid = blockIdx.x * blockDim.x + threadIdx.x;
    if (tid == 0) g_gcount = 0;                // self-clean for next replay
    if (tid >= G * NHEADS) return;
    int head = tid / G;
    int g    = tid - head * G;
    int node = g * NPG + GENE0 + head;

    float dv = g_dinv[node];
    float tn = dv * (g_raw[node] + g_u[node]); // t inline

    float m[16];
#pragma unroll
    for (int c = 0; c < 16; c++) m[c] = 0.f;
#pragma unroll
    for (int k = 0; k < 16; k++) {
        float h = fmaxf(fmaf(tn, __ldg(W1 + k), __ldg(b1 + k)), 0.f);
#pragma unroll
        for (int c = 0; c < 16; c++) m[c] = fmaf(h, __ldg(W2 + k * 16 + c), m[c]);
    }

    int gi = (g * NHEADS + head) * 16;
    float h2[16];
#pragma unroll
    for (int c = 0; c < 16; c++) {
        float a = dv * (g_agg2[gi + c] + dv * m[c]) + __ldg(b2 + c);
        h2[c] = fmaxf(a, 0.f);
    }

    float pred = __ldg(fb2 + head);
#pragma unroll
    for (int j = 0; j < 8; j++) {
        float z = __ldg(fb1 + head * 8 + j);
#pragma unroll
        for (int c = 0; c < 16; c++)
            z = fmaf(h2[c], __ldg(fw1 + head * 128 + c * 8 + j), z);
        z = fmaxf(z, 0.f);
        pred = fmaf(z, __ldg(fw2 + head * 8 + j), pred);
    }
    out[head * G + g] = pred;
}

// ---------------------------------------------------------------------------
extern "C" void kernel_launch(void* const* d_in, const int* in_sizes, int n_in,
                              void* d_out, int out_size) {
    const float* x   = (const float*)d_in[0];
    const int*   ei  = (const int*)  d_in[1];
    const float* W1  = (const float*)d_in[3];
    const float* b1  = (const float*)d_in[4];
    const float* W2  = (const float*)d_in[5];
    const float* b2  = (const float*)d_in[6];
    const float* fw1 = (const float*)d_in[7];
    const float* fb1 = (const float*)d_in[8];
    const float* fw2 = (const float*)d_in[9];
    const float* fb2 = (const float*)d_in[10];
    float* out = (float*)d_out;

    int N = in_sizes[0];             // x is [N,1]   (732160, div by 4)
    int E = in_sizes[1] / 2;         // edge_index is [2,E]  (E div by 4)
    int G = in_sizes[2] / NHEADS;    // y is [G*9]

    const int* src = ei;
    const int* dst = ei + E;

    int n4 = N / 4;
    int e4 = E / 4;
    int a4 = (G * NHEADS * 16) / 4;

    const int B = 256;

    k_deg<<<(e4 + B - 1) / B, B>>>(src, dst, e4);
    k_node1<<<(n4 + B - 1) / B, B>>>(x, n4, a4);
    k_scatter<<<(e4 + B - 1) / B, B>>>(src, dst, e4);
    k_l2<<<1024, B>>>(src, dst, W1, b1, W2);
    k_final<<<(G * NHEADS + 31) / 32, 32>>>(W1, b1, W2, b2, fw1, fb1, fw2, fb2, out, G);
}